// round 2
// baseline (speedup 1.0000x reference)
#include <cuda_runtime.h>
#include <cuda_bf16.h>

// HierarchicalSoftmaxLoss: depth-2 tree, B=128, BATCH=4096, PRED_SIZE=16512.
// loss(row) = LSE(pred[0:128]) - pred[p]
//           + LSE(pred[128+p*128 : +128]) - pred[128+p*128+c]
// p = target>>7, c = target&127. Output = mean over batch.
//
// Single fused kernel: one warp per row, float4 loads, shfl reductions,
// per-CTA atomicAdd into __device__ scratch, last CTA (atomicInc counter,
// wrap=auto-reset) writes d_out and resets scratch for the next graph replay.

#define HSM_B        128
#define HSM_BATCH    4096
#define HSM_PRED     16512
#define WARPS_PER_CTA 8
#define GRID_CTAS    (HSM_BATCH / WARPS_PER_CTA)   // 512

__device__ float        g_hsm_scratch = 0.0f;
__device__ unsigned int g_hsm_count   = 0u;

__device__ __forceinline__ float warp_lse_and_pick(float4 v, int idx, float& picked) {
    // 32 lanes hold 128 floats (lane l holds elements 4l..4l+3).
    float m = fmaxf(fmaxf(v.x, v.y), fmaxf(v.z, v.w));
    #pragma unroll
    for (int o = 16; o; o >>= 1) m = fmaxf(m, __shfl_xor_sync(0xFFFFFFFFu, m, o));
    float s = __expf(v.x - m) + __expf(v.y - m) + __expf(v.z - m) + __expf(v.w - m);
    #pragma unroll
    for (int o = 16; o; o >>= 1) s += __shfl_xor_sync(0xFFFFFFFFu, s, o);
    // idx is warp-uniform: pick locally, broadcast from owning lane.
    const float* e = reinterpret_cast<const float*>(&v);
    float local = e[idx & 3];
    picked = __shfl_sync(0xFFFFFFFFu, local, idx >> 2);
    return __logf(s) + m;
}

__global__ __launch_bounds__(WARPS_PER_CTA * 32)
void hsm_loss_kernel(const float* __restrict__ pred,
                     const int*   __restrict__ targets,
                     float*       __restrict__ out) {
    __shared__ float warp_loss[WARPS_PER_CTA];
    __shared__ bool  is_last;

    const int warp = threadIdx.x >> 5;
    const int lane = threadIdx.x & 31;
    const int row  = blockIdx.x * WARPS_PER_CTA + warp;

    const float* rowp = pred + (size_t)row * HSM_PRED;
    const int t = __ldg(targets + row);
    const int p = t >> 7;      // parent index
    const int c = t & 127;     // child index

    // Level 1: root segment (independent of t -> overlaps target-load latency)
    float4 v1 = reinterpret_cast<const float4*>(rowp)[lane];
    // Level 2: child segment (16B-aligned; offset multiple of 128 floats)
    float4 v2 = reinterpret_cast<const float4*>(rowp + HSM_B + p * HSM_B)[lane];

    float tgt1, tgt2;
    float lse1 = warp_lse_and_pick(v1, p, tgt1);
    float lse2 = warp_lse_and_pick(v2, c, tgt2);
    float loss = (lse1 - tgt1) + (lse2 - tgt2);

    if (lane == 0) warp_loss[warp] = loss;
    __syncthreads();

    if (threadIdx.x == 0) {
        float s = 0.0f;
        #pragma unroll
        for (int w = 0; w < WARPS_PER_CTA; w++) s += warp_loss[w];
        atomicAdd(&g_hsm_scratch, s);
        __threadfence();
        // atomicInc wraps to 0 after reaching GRID_CTAS-1 -> self-resetting counter.
        unsigned prev = atomicInc(&g_hsm_count, GRID_CTAS - 1);
        is_last = (prev == GRID_CTAS - 1);
    }
    __syncthreads();

    if (is_last && threadIdx.x == 0) {
        float total = g_hsm_scratch;
        out[0] = total * (1.0f / HSM_BATCH);
        g_hsm_scratch = 0.0f;   // reset for next graph replay
        __threadfence();
    }
}

extern "C" void kernel_launch(void* const* d_in, const int* in_sizes, int n_in,
                              void* d_out, int out_size) {
    const float* pred    = (const float*)d_in[0];
    const int*   targets = (const int*)d_in[1];
    float*       out     = (float*)d_out;

    hsm_loss_kernel<<<GRID_CTAS, WARPS_PER_CTA * 32>>>(pred, targets, out);
}